// round 17
// baseline (speedup 1.0000x reference)
#include <cuda_runtime.h>
#include <math.h>

#define N_SENT      262144
#define N_BAGS      4096
#define HIDDEN      256
#define NUM_CLASSES 53
#define OUT_ELEMS   (N_BAGS * NUM_CLASSES)  // 217088

#define K1_GRID     2048
#define N_QUADS     (N_SENT / 4)            // 65536
#define K1_WARPS    (K1_GRID * 8)           // 16384 -> 4 quads per warp

// Static scratch (no allocs allowed).
__device__ float2 g_logits[N_SENT];        // logits, then unnormalized e
__device__ float2 g_stats[N_BAGS];         // (1/sum0, 1/sum1), 0 if empty
__device__ float  g_repre[N_BAGS * 512];   // [B, 2*HIDDEN]

// ---------------------------------------------------------------------------
// K1: per-sentence logits. Grid-stride: each warp handles 4 quads with the
//     NEXT quad's label-index int4 prefetched one iteration ahead, removing
//     the li->e serial chain from the critical path.
//     Also initializes out with bias (K3 accumulates with atomics).
// ---------------------------------------------------------------------------
__global__ __launch_bounds__(256, 4) void logits_kernel(
    const float4* __restrict__ x4,     // [N_SENT, 64]
    const float*  __restrict__ e0,     // [14, 256]
    const float*  __restrict__ e1,     // [53, 256]
    const int*    __restrict__ rl,     // [53, 2]
    const int*    __restrict__ li,     // [N_SENT]
    const float*  __restrict__ bias,   // [53]
    float*        __restrict__ out)    // [N_BAGS, 53]
{
    const int warp = threadIdx.x >> 5;
    const int lane = threadIdx.x & 31;
    const int wgid = blockIdx.x * 8 + warp;         // 0..16383

    {   // init out = bias
        int g = blockIdx.x * 256 + threadIdx.x;
        if (g < OUT_ELEMS) out[g] = __ldg(bias + g % NUM_CLASSES);
    }

    const int4* li4 = reinterpret_cast<const int4*>(li);

    int q = wgid;
    int4 liv = __ldg(li4 + q);

    #pragma unroll
    for (int it = 0; it < 4; it++) {
        // prefetch next quad's labels (off critical path for next iteration)
        int4 nliv;
        if (it < 3) nliv = __ldg(li4 + q + K1_WARPS);

        const int base = q * 4;
        const float4* xp = x4 + (size_t)base * 64;

        // 8 independent x loads batched up front
        float4 XA[4], XB[4];
        #pragma unroll
        for (int s = 0; s < 4; s++) {
            XA[s] = __ldg(xp + s * 64 + lane);
            XB[s] = __ldg(xp + s * 64 + 32 + lane);
        }

        int cs[4] = {liv.x, liv.y, liv.z, liv.w};
        float g0[4], g1[4];
        #pragma unroll
        for (int s = 0; s < 4; s++) {
            int l0 = __ldg(rl + 2 * cs[s]);
            int l1 = __ldg(rl + 2 * cs[s] + 1);
            const float4* p0 = reinterpret_cast<const float4*>(e0 + l0 * HIDDEN);
            const float4* p1 = reinterpret_cast<const float4*>(e1 + l1 * HIDDEN);
            float4 ea = __ldg(p0 + lane), eb = __ldg(p0 + 32 + lane);
            float4 fa = __ldg(p1 + lane), fb = __ldg(p1 + 32 + lane);
            float4 xa = XA[s], xb = XB[s];
            g0[s] = xa.x*ea.x + xa.y*ea.y + xa.z*ea.z + xa.w*ea.w
                  + xb.x*eb.x + xb.y*eb.y + xb.z*eb.z + xb.w*eb.w;
            g1[s] = xa.x*fa.x + xa.y*fa.y + xa.z*fa.z + xa.w*fa.w
                  + xb.x*fb.x + xb.y*fb.y + xb.z*fb.z + xb.w*fb.w;
        }

        #pragma unroll
        for (int s = 0; s < 4; s++) {
            #pragma unroll
            for (int o = 16; o; o >>= 1) {
                g0[s] += __shfl_xor_sync(0xffffffffu, g0[s], o);
                g1[s] += __shfl_xor_sync(0xffffffffu, g1[s], o);
            }
        }
        if (lane == 0) {
            #pragma unroll
            for (int s = 0; s < 4; s++)
                g_logits[base + s] = make_float2(g0[s], g1[s]);
        }

        liv = nliv;
        q += K1_WARPS;
    }
}

// ---------------------------------------------------------------------------
// K2a: warp-per-bag softmax. Rewrites g_logits with unnormalized e,
//      stores 1/sum (0 for empty bag) in g_stats.
// ---------------------------------------------------------------------------
__global__ __launch_bounds__(256) void weights_kernel(
    const int* __restrict__ scope)     // [N_BAGS + 1]
{
    const int warp = threadIdx.x >> 5;
    const int lane = threadIdx.x & 31;
    const int bag  = blockIdx.x * 8 + warp;   // grid 512 covers N_BAGS

    const int s0 = __ldg(scope + bag);
    const int s1 = __ldg(scope + bag + 1);

    float m0 = -INFINITY, m1 = -INFINITY;
    for (int i = s0 + lane; i < s1; i += 32) {
        float2 v = g_logits[i];
        m0 = fmaxf(m0, v.x); m1 = fmaxf(m1, v.y);
    }
    #pragma unroll
    for (int o = 16; o; o >>= 1) {
        m0 = fmaxf(m0, __shfl_xor_sync(0xffffffffu, m0, o));
        m1 = fmaxf(m1, __shfl_xor_sync(0xffffffffu, m1, o));
    }

    float s0v = 0.f, s1v = 0.f;
    for (int i = s0 + lane; i < s1; i += 32) {
        float2 v = g_logits[i];
        float e0v = __expf(v.x - m0);
        float e1v = __expf(v.y - m1);
        s0v += e0v; s1v += e1v;
        g_logits[i] = make_float2(e0v, e1v);
    }
    #pragma unroll
    for (int o = 16; o; o >>= 1) {
        s0v += __shfl_xor_sync(0xffffffffu, s0v, o);
        s1v += __shfl_xor_sync(0xffffffffu, s1v, o);
    }
    if (lane == 0)
        g_stats[bag] = make_float2(s0v > 0.f ? 1.0f / s0v : 0.f,
                                   s1v > 0.f ? 1.0f / s1v : 0.f);
}

// ---------------------------------------------------------------------------
// K2: one block per bag. Warp = sentence subgroup (stride 8), lane covers
//     float4 columns lane and lane+32. Uniform __ldg weight broadcasts,
//     flat loop, single-barrier combine. (Unchanged from R16.)
// ---------------------------------------------------------------------------
__global__ __launch_bounds__(256, 4) void bag_kernel(
    const float4* __restrict__ x4,     // [N_SENT, 64]
    const int*    __restrict__ scope)  // [N_BAGS + 1]
{
    __shared__ float s_c[8 * 512];     // 16 KB combine scratch

    const int b    = blockIdx.x;
    const int tid  = threadIdx.x;
    const int lane = tid & 31;
    const int w    = tid >> 5;         // subgroup 0..7

    const int s0 = __ldg(scope + b);
    const int s1 = __ldg(scope + b + 1);
    const float2 iv = g_stats[b];

    float4 A0a = make_float4(0.f,0.f,0.f,0.f), A0b = make_float4(0.f,0.f,0.f,0.f);
    float4 A1a = make_float4(0.f,0.f,0.f,0.f), A1b = make_float4(0.f,0.f,0.f,0.f);

    const float2* wl = reinterpret_cast<const float2*>(g_logits);

    int j = s0 + w;
    for (; j + 8 < s1; j += 16) {
        float2 w0 = __ldg(wl + j);
        float2 w1 = __ldg(wl + j + 8);
        const float4* r0 = x4 + (size_t)j * 64;
        const float4* r1 = x4 + (size_t)(j + 8) * 64;
        float4 xa0 = __ldg(r0 + lane);
        float4 xb0 = __ldg(r0 + 32 + lane);
        float4 xa1 = __ldg(r1 + lane);
        float4 xb1 = __ldg(r1 + 32 + lane);

        A0a.x += w0.x*xa0.x; A0a.y += w0.x*xa0.y; A0a.z += w0.x*xa0.z; A0a.w += w0.x*xa0.w;
        A1a.x += w0.y*xa0.x; A1a.y += w0.y*xa0.y; A1a.z += w0.y*xa0.z; A1a.w += w0.y*xa0.w;
        A0b.x += w0.x*xb0.x; A0b.y += w0.x*xb0.y; A0b.z += w0.x*xb0.z; A0b.w += w0.x*xb0.w;
        A1b.x += w0.y*xb0.x; A1b.y += w0.y*xb0.y; A1b.z += w0.y*xb0.z; A1b.w += w0.y*xb0.w;
        A0a.x += w1.x*xa1.x; A0a.y += w1.x*xa1.y; A0a.z += w1.x*xa1.z; A0a.w += w1.x*xa1.w;
        A1a.x += w1.y*xa1.x; A1a.y += w1.y*xa1.y; A1a.z += w1.y*xa1.z; A1a.w += w1.y*xa1.w;
        A0b.x += w1.x*xb1.x; A0b.y += w1.x*xb1.y; A0b.z += w1.x*xb1.z; A0b.w += w1.x*xb1.w;
        A1b.x += w1.y*xb1.x; A1b.y += w1.y*xb1.y; A1b.z += w1.y*xb1.z; A1b.w += w1.y*xb1.w;
    }
    if (j < s1) {
        float2 w0 = __ldg(wl + j);
        const float4* r0 = x4 + (size_t)j * 64;
        float4 xa0 = __ldg(r0 + lane);
        float4 xb0 = __ldg(r0 + 32 + lane);
        A0a.x += w0.x*xa0.x; A0a.y += w0.x*xa0.y; A0a.z += w0.x*xa0.z; A0a.w += w0.x*xa0.w;
        A1a.x += w0.y*xa0.x; A1a.y += w0.y*xa0.y; A1a.z += w0.y*xa0.z; A1a.w += w0.y*xa0.w;
        A0b.x += w0.x*xb0.x; A0b.y += w0.x*xb0.y; A0b.z += w0.x*xb0.z; A0b.w += w0.x*xb0.w;
        A1b.x += w0.y*xb0.x; A1b.y += w0.y*xb0.y; A1b.z += w0.y*xb0.z; A1b.w += w0.y*xb0.w;
    }

    // single-barrier combine: s_c[w][level*256 + dim]
    __syncthreads();
    *reinterpret_cast<float4*>(&s_c[w * 512 + 4 * lane])       = A0a;
    *reinterpret_cast<float4*>(&s_c[w * 512 + 128 + 4 * lane]) = A0b;
    *reinterpret_cast<float4*>(&s_c[w * 512 + 256 + 4 * lane]) = A1a;
    *reinterpret_cast<float4*>(&s_c[w * 512 + 384 + 4 * lane]) = A1b;
    __syncthreads();

    float r0 = 0.f, r1 = 0.f;
    #pragma unroll
    for (int g = 0; g < 8; g++) {
        r0 += s_c[g * 512 + tid];
        r1 += s_c[g * 512 + 256 + tid];
    }
    g_repre[(size_t)b * 512 + tid]       = r0 * iv.x;
    g_repre[(size_t)b * 512 + 256 + tid] = r1 * iv.y;
}

// ---------------------------------------------------------------------------
// K3: out += repre @ disc^T, split-k atomics. grid (64 bag-groups, 4 kc).
//     Warp owns 8 bags x 2 classes; rep via warp-broadcast LDS.
//     out pre-initialized with bias in K1. (Unchanged from R16.)
// ---------------------------------------------------------------------------
#define G_BAGS 64
__global__ __launch_bounds__(256) void gemm_kernel(
    const float* __restrict__ disc,    // [53, 512]
    float*       __restrict__ out)     // [N_BAGS, 53]
{
    __shared__ float s_rep[G_BAGS * 128];        // 32 KB (k-chunk of 64 bags)
    __shared__ float s_disc[NUM_CLASSES * 132];  // ~28 KB, pitch 132 floats

    const int tid  = threadIdx.x;
    const int lane = tid & 31;
    const int w    = tid >> 5;
    const int bag0 = blockIdx.x * G_BAGS;
    const int kc   = blockIdx.y;                 // k-chunk 0..3 (128 floats)

    const float4* rep4 = reinterpret_cast<const float4*>(g_repre);
    float4* srep4 = reinterpret_cast<float4*>(s_rep);
    for (int f = tid; f < G_BAGS * 32; f += 256) {
        int bg = f >> 5, q = f & 31;
        srep4[bg * 32 + q] = rep4[(size_t)(bag0 + bg) * 128 + kc * 32 + q];
    }
    for (int f = tid; f < NUM_CLASSES * 32; f += 256) {
        int c = f >> 5, q = f & 31;
        *reinterpret_cast<float4*>(&s_disc[c * 132 + q * 4]) =
            __ldg(reinterpret_cast<const float4*>(disc) + c * 128 + kc * 32 + q);
    }
    __syncthreads();

    const int c1  = 32 + lane;
    const int c1c = (c1 < NUM_CLASSES) ? c1 : lane;

    float accA[8] = {0.f,0.f,0.f,0.f,0.f,0.f,0.f,0.f};
    float accB[8] = {0.f,0.f,0.f,0.f,0.f,0.f,0.f,0.f};

    const float4* sd = reinterpret_cast<const float4*>(s_disc);  // pitch 33 f4
    #pragma unroll 4
    for (int q = 0; q < 32; q++) {
        float4 d0 = sd[lane * 33 + q];
        float4 d1 = sd[c1c * 33 + q];
        #pragma unroll
        for (int i = 0; i < 8; i++) {
            float4 r = srep4[(w * 8 + i) * 32 + q];   // warp-broadcast
            accA[i] += r.x*d0.x + r.y*d0.y + r.z*d0.z + r.w*d0.w;
            accB[i] += r.x*d1.x + r.y*d1.y + r.z*d1.z + r.w*d1.w;
        }
    }

    #pragma unroll
    for (int i = 0; i < 8; i++) {
        int bb = bag0 + w * 8 + i;
        atomicAdd(&out[bb * NUM_CLASSES + lane], accA[i]);
        if (c1 < NUM_CLASSES)
            atomicAdd(&out[bb * NUM_CLASSES + c1], accB[i]);
    }
}

// ---------------------------------------------------------------------------
extern "C" void kernel_launch(void* const* d_in, const int* in_sizes, int n_in,
                              void* d_out, int out_size)
{
    const float* x    = (const float*)d_in[0];   // [262144, 256]
    const float* e0   = (const float*)d_in[1];   // [14, 256]
    const float* e1   = (const float*)d_in[2];   // [53, 256]
    const float* disc = (const float*)d_in[3];   // [53, 512]
    const float* bias = (const float*)d_in[4];   // [53]
    const int*   rl   = (const int*)d_in[5];     // [53, 2]
    const int*   li   = (const int*)d_in[6];     // [262144]
    const int*   sc   = (const int*)d_in[7];     // [4097]
    float* out = (float*)d_out;                  // [4096, 53]

    logits_kernel<<<K1_GRID, 256>>>((const float4*)x, e0, e1, rl, li, bias, out);
    weights_kernel<<<N_BAGS / 8, 256>>>(sc);
    bag_kernel<<<N_BAGS, 256>>>((const float4*)x, sc);
    gemm_kernel<<<dim3(N_BAGS / G_BAGS, 4), 256>>>(disc, out);
}